// round 6
// baseline (speedup 1.0000x reference)
#include <cuda_runtime.h>
#include <cstdint>

// BroadcastTC on GB300, round 6: fully warp-synchronous. Each warp owns 16
// pairs; pair k in warp handled by lanes 2k (role 0) and 2k+1 (role 1).
// No block barriers; cp.async input staging; shuffle-based partial exchange.
//   out1[xy,uv] = sum_k t1[xy*3+k]*t2[k*9+uv] / sqrt(3)   (81 floats)
//   out2[x,u]   = sum_kl t1[x*9+kl]*t2[kl*3+u] / 3        (9 floats)
//   out3        = dot(t1,t2) / sqrt(27)                   (1 float)
// Output layout: [out1 flat | out2 flat | out3 flat].

#define THREADS 256
#define WARPS   8
#define PPW     16
#define PPB     (WARPS * PPW)   // 128 pairs per block

__device__ __forceinline__ uint32_t smem_u32(const void* p) {
    uint32_t a;
    asm("{ .reg .u64 t; cvta.to.shared.u64 t, %1; cvt.u32.u64 %0, t; }"
        : "=r"(a) : "l"(p));
    return a;
}

__global__ __launch_bounds__(THREADS, 4)
void broadcast_tc_kernel(const float* __restrict__ T1,
                         const float* __restrict__ T2,
                         float* __restrict__ out,
                         int npairs)
{
    // Per-warp private buffer, reused 3x:
    //   phase A: t1 at floats [0..431], t2 at [432..863]
    //   phase B: out1 staging [0..1295]
    //   phase C: out2 staging [0..143]
    __shared__ __align__(16) float wbuf[WARPS][PPW * 81];   // 8 x 5184 B

    const int tid  = threadIdx.x;
    const int w    = tid >> 5;
    const int lane = tid & 31;
    const int k    = lane >> 1;     // pair within warp
    const int role = lane & 1;
    const long long pw = (long long)blockIdx.x * PPB + (long long)w * PPW;

    float* wb = wbuf[w];

    // ---- Phase A: stage this warp's 16 pairs of inputs via cp.async ----
    {
        const float4* g1 = (const float4*)(T1 + pw * 27);   // 108 float4
        const float4* g2 = (const float4*)(T2 + pw * 27);   // 108 float4
        const uint32_t sb = smem_u32(wb);
        #pragma unroll
        for (int t = 0; t < 7; t++) {
            const int i = lane + t * 32;
            if (i < 216) {
                const float4* src = (i < 108) ? (g1 + i) : (g2 + (i - 108));
                asm volatile("cp.async.cg.shared.global [%0], [%1], 16;"
                             :: "r"(sb + i * 16), "l"(src) : "memory");
            }
        }
        asm volatile("cp.async.commit_group;" ::: "memory");
        asm volatile("cp.async.wait_group 0;" ::: "memory");
        __syncwarp();
    }

    // ---- Register gather (b broadcast across role pair; a 2-way max) ----
    float b[27];
    #pragma unroll
    for (int j = 0; j < 27; j++) b[j] = wb[432 + k * 27 + j];
    float a[15];   // a[j] = t1[role*12 + j]
    {
        const int ab = k * 27 + role * 12;
        #pragma unroll
        for (int j = 0; j < 15; j++) a[j] = wb[ab + j];
    }
    __syncwarp();   // inputs consumed; wb reusable for out1 staging

    const float n1 = 0.5773502691896258f;   // 1/sqrt(3)
    const float n2 = 0.3333333333333333f;   // 1/3
    const float n3 = 0.1924500897298753f;   // 1/sqrt(27)

    const int sb81 = k * 81;
    float e[4];    // cross-role partials: x1p[0..2], out3 partial
    float q[3];    // role0: out2 x=0 (scaled); role1: out2 x=2 (scaled)
    float x1[3];   // combined out2 x=1 (role1 only, after shuffle)

    if (role == 0) {
        // out1 rows xy = 0..3
        #pragma unroll
        for (int xy = 0; xy < 4; xy++) {
            const float c0 = a[xy * 3 + 0] * n1;
            const float c1 = a[xy * 3 + 1] * n1;
            const float c2 = a[xy * 3 + 2] * n1;
            #pragma unroll
            for (int uv = 0; uv < 9; uv++)
                wb[sb81 + xy * 9 + uv] = c0 * b[uv] + c1 * b[9 + uv] + c2 * b[18 + uv];
        }
        // out2 x=0 full: t1[kl] = a[kl]
        #pragma unroll
        for (int u = 0; u < 3; u++) {
            float r = 0.0f;
            #pragma unroll
            for (int kl = 0; kl < 9; kl++) r += a[kl] * b[kl * 3 + u];
            q[u] = r * n2;
        }
        // out2 x=1 partial, kl=0..2: t1[9+kl] = a[9+kl]
        #pragma unroll
        for (int u = 0; u < 3; u++)
            e[u] = a[9] * b[u] + a[10] * b[3 + u] + a[11] * b[6 + u];
        // out3 partial j=0..11
        float d = 0.0f;
        #pragma unroll
        for (int j = 0; j < 12; j++) d += a[j] * b[j];
        e[3] = d;
    } else {
        // a[j] = t1[12+j]
        // out1 rows xy = 4..8: t1[xy*3+k] = a[xy*3-12+k]
        #pragma unroll
        for (int xy = 4; xy < 9; xy++) {
            const float c0 = a[xy * 3 - 12] * n1;
            const float c1 = a[xy * 3 - 11] * n1;
            const float c2 = a[xy * 3 - 10] * n1;
            #pragma unroll
            for (int uv = 0; uv < 9; uv++)
                wb[sb81 + xy * 9 + uv] = c0 * b[uv] + c1 * b[9 + uv] + c2 * b[18 + uv];
        }
        // out2 x=1 partial, kl=3..8: t1[9+kl] = t1[12..17] = a[kl-3]
        #pragma unroll
        for (int u = 0; u < 3; u++) {
            float r = 0.0f;
            #pragma unroll
            for (int kl = 3; kl < 9; kl++) r += a[kl - 3] * b[kl * 3 + u];
            e[u] = r;
        }
        // out2 x=2 full: t1[18+kl] = a[6+kl]
        #pragma unroll
        for (int u = 0; u < 3; u++) {
            float r = 0.0f;
            #pragma unroll
            for (int kl = 0; kl < 9; kl++) r += a[6 + kl] * b[kl * 3 + u];
            q[u] = r * n2;
        }
        // out3 partial j=12..26
        float d = 0.0f;
        #pragma unroll
        for (int j = 0; j < 15; j++) d += a[j] * b[12 + j];
        e[3] = d;
    }

    // ---- Convergent role exchange via shuffles ----
    float r0 = __shfl_xor_sync(0xffffffffu, e[0], 1);
    float r1 = __shfl_xor_sync(0xffffffffu, e[1], 1);
    float r2 = __shfl_xor_sync(0xffffffffu, e[2], 1);
    float r3 = __shfl_xor_sync(0xffffffffu, e[3], 1);

    if (role == 1) {
        x1[0] = (e[0] + r0) * n2;
        x1[1] = (e[1] + r1) * n2;
        x1[2] = (e[2] + r2) * n2;
        // out3: 16 contiguous scalars from odd lanes
        out[(long long)npairs * 90 + pw + k] = (e[3] + r3) * n3;
    }

    __syncwarp();   // out1 staging complete for this warp

    // ---- Copy out1: 324 float4, contiguous per warp ----
    {
        float4* o1 = (float4*)(out + pw * 81);
        const float4* sv = (const float4*)wb;
        #pragma unroll
        for (int t = 0; t < 11; t++) {
            const int i = lane + t * 32;
            if (i < 324) o1[i] = sv[i];
        }
    }
    __syncwarp();   // wb free

    // ---- Stage + copy out2: 144 floats = 36 float4 per warp ----
    if (role == 0) {
        wb[k * 9 + 0] = q[0];
        wb[k * 9 + 1] = q[1];
        wb[k * 9 + 2] = q[2];
    } else {
        wb[k * 9 + 3] = x1[0];
        wb[k * 9 + 4] = x1[1];
        wb[k * 9 + 5] = x1[2];
        wb[k * 9 + 6] = q[0];
        wb[k * 9 + 7] = q[1];
        wb[k * 9 + 8] = q[2];
    }
    __syncwarp();
    {
        float4* o2 = (float4*)(out + (long long)npairs * 81 + pw * 9);
        const float4* sv = (const float4*)wb;
        #pragma unroll
        for (int t = 0; t < 2; t++) {
            const int i = lane + t * 32;
            if (i < 36) o2[i] = sv[i];
        }
    }
}

extern "C" void kernel_launch(void* const* d_in, const int* in_sizes, int n_in,
                              void* d_out, int out_size)
{
    const float* T1 = (const float*)d_in[0];
    const float* T2 = (const float*)d_in[1];
    float* out = (float*)d_out;

    const int npairs = in_sizes[0] / 27;     // 1,048,576
    const int grid = npairs / PPB;           // 8192

    broadcast_tc_kernel<<<grid, THREADS>>>(T1, T2, out, npairs);
}

// round 7
// speedup vs baseline: 1.0129x; 1.0129x over previous
#include <cuda_runtime.h>

// BroadcastTC on GB300, round 7: R5 structure with finer block granularity
// (64 pairs / 128 threads -> 8 independent blocks per SM) + streaming cache
// hints (__ldcs/__stcs) to keep the write stream from thrashing L2.
// npairs = B*C = 1,048,576; t1,t2 = 27 fp32 per pair.
//   out1[xy,uv] = sum_k t1[xy*3+k]*t2[k*9+uv] / sqrt(3)   (81 floats)
//   out2[x,u]   = sum_kl t1[x*9+kl]*t2[kl*3+u] / 3        (9 floats)
//   out3        = dot(t1,t2) / sqrt(27)                   (1 float)
// Output layout: [out1 flat | out2 flat | out3 flat].
//
// Role split (warp-uniform): threads p (role 0) and p+64 (role 1) share pair p.
//   role 0: t1[0..11]  -> out1 rows xy=0..3, out2 x=0, x=1 partial(kl=0..2),
//           out3 partial(j=0..11)
//   role 1: t1[12..26] -> out1 rows xy=4..8, out2 x=1 partial(kl=3..8), x=2,
//           out3 partial(j=12..26), combines + stores out3

#define PPB 64
#define THREADS 128

__global__ __launch_bounds__(THREADS, 8)
void broadcast_tc_kernel(const float* __restrict__ T1,
                         const float* __restrict__ T2,
                         float* __restrict__ out,
                         int npairs)
{
    __shared__ __align__(16) float s[PPB * 81];   // 20736 B: inputs, then staging
    __shared__ float aux[PPB * 4];                // 1024 B: role-0 partials

    const int tid  = threadIdx.x;
    const int p    = tid & (PPB - 1);
    const int role = tid >> 6;                    // warp-uniform
    const long long p0 = (long long)blockIdx.x * PPB;

    // ---- Stage inputs coalesced (streaming loads): 2 x 432 float4 ----
    {
        const float4* g1 = (const float4*)(T1 + p0 * 27);
        const float4* g2 = (const float4*)(T2 + p0 * 27);
        float4* sv = (float4*)s;
        #pragma unroll
        for (int i = tid; i < PPB * 27 / 4; i += THREADS) {
            sv[i]                = __ldcs(g1 + i);
            sv[PPB * 27 / 4 + i] = __ldcs(g2 + i);
        }
    }
    __syncthreads();

    // ---- Per-role register gather (stride 27: conflict-free) ----
    float b[27], a[15];   // a[j] = t1[role*12 + j]
    #pragma unroll
    for (int j = 0; j < 27; j++) b[j] = s[PPB * 27 + p * 27 + j];
    {
        const int abase = p * 27 + role * 12;
        #pragma unroll
        for (int j = 0; j < 15; j++) a[j] = s[abase + j];
    }
    __syncthreads();   // inputs consumed; s reusable

    const float n1 = 0.5773502691896258f;   // 1/sqrt(3)
    const float n2 = 0.3333333333333333f;   // 1/3
    const float n3 = 0.1924500897298753f;   // 1/sqrt(27)

    if (role == 0) {
        // out1 rows xy = 0..3
        #pragma unroll
        for (int xy = 0; xy < 4; xy++) {
            const float c0 = a[xy * 3 + 0] * n1;
            const float c1 = a[xy * 3 + 1] * n1;
            const float c2 = a[xy * 3 + 2] * n1;
            #pragma unroll
            for (int uv = 0; uv < 9; uv++)
                s[p * 81 + xy * 9 + uv] = c0 * b[uv] + c1 * b[9 + uv] + c2 * b[18 + uv];
        }

        // out2 x=0 full
        float x0[3];
        #pragma unroll
        for (int u = 0; u < 3; u++) {
            float r = 0.0f;
            #pragma unroll
            for (int kl = 0; kl < 9; kl++) r += a[kl] * b[kl * 3 + u];
            x0[u] = r * n2;
        }
        // out2 x=1 partial, kl=0..2 (t1[9..11])
        float x1p[3];
        #pragma unroll
        for (int u = 0; u < 3; u++)
            x1p[u] = a[9] * b[u] + a[10] * b[3 + u] + a[11] * b[6 + u];
        // out3 partial j=0..11
        float d = 0.0f;
        #pragma unroll
        for (int j = 0; j < 12; j++) d += a[j] * b[j];

        aux[p * 4 + 0] = x1p[0];
        aux[p * 4 + 1] = x1p[1];
        aux[p * 4 + 2] = x1p[2];
        aux[p * 4 + 3] = d;

        __syncthreads();   // out1 staged, partials published

        // copy out1 coalesced (both roles), streaming stores
        {
            float4* o1 = (float4*)(out + p0 * 81);
            const float4* sv = (const float4*)s;
            for (int i = tid; i < PPB * 81 / 4; i += THREADS) __stcs(o1 + i, sv[i]);
        }
        __syncthreads();   // s free

        // stage out2 x=0 -> slots 0..2
        s[p * 9 + 0] = x0[0];
        s[p * 9 + 1] = x0[1];
        s[p * 9 + 2] = x0[2];
        __syncthreads();

        // copy out2 coalesced
        {
            float4* o2 = (float4*)(out + (long long)npairs * 81 + p0 * 9);
            const float4* sv = (const float4*)s;
            for (int i = tid; i < PPB * 9 / 4; i += THREADS) __stcs(o2 + i, sv[i]);
        }
    } else {
        // a[j] = t1[12+j]
        // out1 rows xy = 4..8: t1[xy*3+k] = a[xy*3-12+k]
        #pragma unroll
        for (int xy = 4; xy < 9; xy++) {
            const float c0 = a[xy * 3 - 12] * n1;
            const float c1 = a[xy * 3 - 11] * n1;
            const float c2 = a[xy * 3 - 10] * n1;
            #pragma unroll
            for (int uv = 0; uv < 9; uv++)
                s[p * 81 + xy * 9 + uv] = c0 * b[uv] + c1 * b[9 + uv] + c2 * b[18 + uv];
        }

        // out2 x=1 partial, kl=3..8: t1[9+kl] = t1[12..17] = a[kl-3]
        float x1p[3];
        #pragma unroll
        for (int u = 0; u < 3; u++) {
            float r = 0.0f;
            #pragma unroll
            for (int kl = 3; kl < 9; kl++) r += a[kl - 3] * b[kl * 3 + u];
            x1p[u] = r;
        }
        // out2 x=2 full: t1[18+kl] = a[6+kl]
        float x2[3];
        #pragma unroll
        for (int u = 0; u < 3; u++) {
            float r = 0.0f;
            #pragma unroll
            for (int kl = 0; kl < 9; kl++) r += a[6 + kl] * b[kl * 3 + u];
            x2[u] = r * n2;
        }
        // out3 partial j=12..26
        float d = 0.0f;
        #pragma unroll
        for (int j = 0; j < 15; j++) d += a[j] * b[12 + j];

        __syncthreads();   // out1 staged, partials visible

        // out3: combine + coalesced streaming store
        __stcs(out + (long long)npairs * 90 + p0 + p, (d + aux[p * 4 + 3]) * n3);

        // combine out2 x=1
        float x1[3];
        #pragma unroll
        for (int u = 0; u < 3; u++) x1[u] = (x1p[u] + aux[p * 4 + u]) * n2;

        // copy out1 coalesced (both roles)
        {
            float4* o1 = (float4*)(out + p0 * 81);
            const float4* sv = (const float4*)s;
            for (int i = tid; i < PPB * 81 / 4; i += THREADS) __stcs(o1 + i, sv[i]);
        }
        __syncthreads();   // s free

        // stage out2 x=1, x=2 -> slots 3..8
        s[p * 9 + 3] = x1[0];
        s[p * 9 + 4] = x1[1];
        s[p * 9 + 5] = x1[2];
        s[p * 9 + 6] = x2[0];
        s[p * 9 + 7] = x2[1];
        s[p * 9 + 8] = x2[2];
        __syncthreads();

        // copy out2 coalesced
        {
            float4* o2 = (float4*)(out + (long long)npairs * 81 + p0 * 9);
            const float4* sv = (const float4*)s;
            for (int i = tid; i < PPB * 9 / 4; i += THREADS) __stcs(o2 + i, sv[i]);
        }
    }
}

extern "C" void kernel_launch(void* const* d_in, const int* in_sizes, int n_in,
                              void* d_out, int out_size)
{
    const float* T1 = (const float*)d_in[0];
    const float* T2 = (const float*)d_in[1];
    float* out = (float*)d_out;

    const int npairs = in_sizes[0] / 27;     // 1,048,576
    const int grid = npairs / PPB;           // 16384

    broadcast_tc_kernel<<<grid, THREADS>>>(T1, T2, out, npairs);
}